// round 4
// baseline (speedup 1.0000x reference)
#include <cuda_runtime.h>

// Problem constants: x [B=8, I=32, O=32, D=8, H=14, W=14, kh=3, kw=3] fp32
// out [B, O, D, H, W] fp32
namespace {
constexpr int Bn = 8, In = 32, On = 32, Dn = 8, Hn = 14, Wn = 14, Kn = 9;
constexpr int WK   = Wn * Kn;   // 126 contiguous floats per (b,i,o,d,h)
constexpr int SLAB = Dn * WK;   // 1008 floats = 4032 B per (b,i,o,h) slab
constexpr int NT   = 256;
constexpr int SUBK = 26;        // ceil(0.8 * 32)
constexpr int NBUF = 4;         // cp.async ring depth (3 in flight)
}

__device__ __forceinline__ void cp_async8(void* sm, const void* gm) {
    unsigned s = (unsigned)__cvta_generic_to_shared(sm);
    asm volatile("cp.async.ca.shared.global [%0], [%1], 8;\n" :: "r"(s), "l"(gm));
}
__device__ __forceinline__ void cp_commit() {
    asm volatile("cp.async.commit_group;\n");
}
template <int N>
__device__ __forceinline__ void cp_wait() {
    asm volatile("cp.async.wait_group %0;\n" :: "n"(N));
}

// single-MUFU approximate math (rel err ~2^-23, far inside 1e-3 budget)
__device__ __forceinline__ float fsqrt_ap(float x) {
    float r; asm("sqrt.approx.f32 %0, %1;" : "=f"(r) : "f"(x)); return r;
}
__device__ __forceinline__ float frcp_ap(float x) {
    float r; asm("rcp.approx.f32 %0, %1;" : "=f"(r) : "f"(x)); return r;
}

// Monotone float -> uint key: a <= b  <=>  fkey(a) <= fkey(b)
__device__ __forceinline__ unsigned fkey(float f) {
    unsigned u = __float_as_uint(f);
    return u ^ (unsigned)(((int)u >> 31) | 0x80000000);
}

__global__ void __launch_bounds__(NT)
caps_route_kernel(const float* __restrict__ x, float* __restrict__ out) {
    const int h = blockIdx.x, o = blockIdx.y, b = blockIdx.z;
    const int tid = threadIdx.x;

    __shared__ __align__(16) float sl[NBUF][SLAB]; // cp.async ring
    __shared__ float    sXavg[In * Dn * Wn];       // [i][d][w]
    __shared__ float    sNI[In * Wn];              // [i][w]
    __shared__ float    sRsum[Wn];                 // 1 / sum_i nI, per w
    __shared__ float    sV[Dn * Wn];               // consensus [d][w]
    __shared__ float    sLoss[In * Wn];            // [i][w]
    __shared__ unsigned sThr[Wn];                  // threshold keys per w
    __shared__ float    sRfin[Wn];                 // 1 / masked sum_i nI

    const long strideD = (long)Hn * Wn * Kn;       // 1764
    const long strideO = Dn * strideD;             // 14112
    const long strideI = On * strideO;             // 451584
    const long strideB = In * strideI;             // 14450688
    const float* base = x + (long)b * strideB + (long)o * strideO + (long)h * WK;

    // ---- hoisted per-thread cp.async offsets (8B granules; SLAB/2 = 504) ----
    const int j0 = tid, j1 = tid + NT;
    const int d0 = j0 / 63, c0 = j0 - 63 * d0;
    const int sOff0 = d0 * WK + 2 * c0;
    const long gOff0 = (long)d0 * strideD + 2 * c0;
    const bool has1 = (j1 < SLAB / 2);
    const int d1 = j1 / 63, c1 = j1 - 63 * d1;
    const int sOff1 = d1 * WK + 2 * c1;
    const long gOff1 = (long)d1 * strideD + 2 * c1;

    // Region A: 224 threads = warps 0..6; 16-lane group per w, lane = k
    const int wA = tid >> 4, kA = tid & 15;
    const bool actA  = (tid < 224);                // uniform per warp
    const bool realA = (kA < Kn);
    const int wkA = wA * Kn + kA;
    // Region C (phase 2 writes): 112 threads, one per (d, w)
    const bool actC = (tid < Dn * Wn);
    const int dC = tid / Wn, wC = tid - dC * Wn;

    if (tid < Wn) sThr[tid] = 0u;

    // ---- prologue: prefetch slabs 0..2 ----
    #pragma unroll
    for (int p = 0; p < NBUF - 1; ++p) {
        const float* g = base + (long)p * strideI;
        cp_async8(&sl[p][sOff0], g + gOff0);
        if (has1) cp_async8(&sl[p][sOff1], g + gOff1);
        cp_commit();
    }

    // ---- Phase 1: per capsule, kernel-position weighted average ----
    for (int i = 0; i < In; ++i) {
        cp_wait<NBUF - 2>();   // slab i's group complete
        __syncthreads();       // data visible to all; prev compute done reading buf (i-1)&3

        // prefetch slab i+3 into buffer (i+3)&3 == (i-1)&3 (safe after barrier)
        if (i + NBUF - 1 < In) {
            const float* g = base + (long)(i + NBUF - 1) * strideI;
            float* dst = sl[(i + NBUF - 1) & (NBUF - 1)];
            cp_async8(&dst[sOff0], g + gOff0);
            if (has1) cp_async8(&dst[sOff1], g + gOff1);
        }
        cp_commit();   // commit (possibly empty) group to keep count in lockstep

        if (actA) {
            const float* s = sl[i & (NBUF - 1)];
            float xr[Dn], pd[Dn];
            float den = 0.f;
            if (realA) {
                float ss = 0.f;
                #pragma unroll
                for (int d = 0; d < Dn; ++d) {
                    xr[d] = s[d * WK + wkA];
                    ss += xr[d] * xr[d];
                }
                float nv = fsqrt_ap(ss);
                #pragma unroll
                for (int d = 0; d < Dn; ++d) pd[d] = nv * xr[d];
                den = nv;
            } else {
                #pragma unroll
                for (int d = 0; d < Dn; ++d) pd[d] = 0.f;
            }
            // 16-lane butterfly: 8 d-partials + denominator
            #pragma unroll
            for (int off = 8; off > 0; off >>= 1) {
                #pragma unroll
                for (int d = 0; d < Dn; ++d)
                    pd[d] += __shfl_xor_sync(0xffffffffu, pd[d], off, 16);
                den += __shfl_xor_sync(0xffffffffu, den, off, 16);
            }
            float r = frcp_ap(den);           // all lanes (cheap enough, avoids bcast)
            if (kA < Dn) {
                float pv = pd[0];
                #pragma unroll
                for (int d = 1; d < Dn; ++d)
                    if (kA == d) pv = pd[d];
                sXavg[(i * Dn + kA) * Wn + wA] = pv * r;
            }
        }
    }
    __syncthreads();

    // ---- Phase 2: reductions over input capsules (all SMEM) ----
    // nI[i][w] = || xavg[i,:,w] ||
    for (int p = tid; p < In * Wn; p += NT) {
        int i = p / Wn, w = p - Wn * i;
        float acc = 0.f;
        #pragma unroll
        for (int d = 0; d < Dn; ++d) {
            float v = sXavg[(i * Dn + d) * Wn + w];
            acc += v * v;
        }
        sNI[p] = fsqrt_ap(acc);
    }
    __syncthreads();

    if (tid < Wn) {
        float sum = 0.f;
        #pragma unroll 4
        for (int i = 0; i < In; ++i) sum += sNI[i * Wn + tid];
        sRsum[tid] = frcp_ap(sum);
    }
    __syncthreads();

    // consensus v[d][w]
    if (actC) {
        float num = 0.f;
        #pragma unroll 4
        for (int i = 0; i < In; ++i)
            num += sNI[i * Wn + wC] * sXavg[(i * Dn + dC) * Wn + wC];
        sV[dC * Wn + wC] = num * sRsum[wC];
    }
    __syncthreads();

    // losses[i][w] = -<v[:, w], xavg[i,:,w]>
    for (int p = tid; p < In * Wn; p += NT) {
        int i = p / Wn, w = p - Wn * i;
        float acc = 0.f;
        #pragma unroll
        for (int d = 0; d < Dn; ++d)
            acc += sV[d * Wn + w] * sXavg[(i * Dn + d) * Wn + w];
        sLoss[p] = -acc;
    }
    __syncthreads();

    // kth-smallest threshold (k = SUBK), exact tie semantics:
    // thr = max{ v : #(x < v) <= SUBK-1 } == sorted[SUBK-1]
    for (int p = tid; p < In * Wn; p += NT) {
        int i = p / Wn, w = p - Wn * i;
        float mine = sLoss[p];
        int cnt = 0;
        #pragma unroll 8
        for (int j = 0; j < In; ++j)
            cnt += (sLoss[j * Wn + w] < mine);
        if (cnt <= SUBK - 1)
            atomicMax(&sThr[w], fkey(mine));
    }
    __syncthreads();

    // masked denominator reciprocal per w
    if (tid < Wn) {
        const unsigned thr = sThr[tid];
        float den = 0.f;
        #pragma unroll 4
        for (int i = 0; i < In; ++i)
            if (fkey(sLoss[i * Wn + tid]) <= thr) den += sNI[i * Wn + tid];
        sRfin[tid] = frcp_ap(den);
    }
    __syncthreads();

    // masked re-average, write output
    if (actC) {
        const unsigned thr = sThr[wC];
        float num = 0.f;
        #pragma unroll 4
        for (int i = 0; i < In; ++i) {
            if (fkey(sLoss[i * Wn + wC]) <= thr)
                num += sNI[i * Wn + wC] * sXavg[(i * Dn + dC) * Wn + wC];
        }
        out[(((long)b * On + o) * Dn + dC) * (Hn * Wn) + h * Wn + wC] = num * sRfin[wC];
    }
}

extern "C" void kernel_launch(void* const* d_in, const int* in_sizes, int n_in,
                              void* d_out, int out_size) {
    const float* x = (const float*)d_in[0];
    float* out = (float*)d_out;
    dim3 grid(Hn, On, Bn);   // 14 x 32 x 8 = 3584 CTAs
    caps_route_kernel<<<grid, NT>>>(x, out);
}

// round 5
// speedup vs baseline: 2.1257x; 2.1257x over previous
#include <cuda_runtime.h>

// x [B=8, I=32, O=32, D=8, H=14, W=14, kh=3, kw=3] fp32 -> out [B, O, D, H, W] fp32
namespace {
constexpr int Bn = 8, In = 32, On = 32, Dn = 8, Hn = 14, Wn = 14, Kn = 9;
constexpr int WK    = Wn * Kn;     // 126 contiguous floats per (b,i,o,d,h)
constexpr int PK    = 11;          // padded k-stride (odd -> conflict-free + 8B-aligned copy)
constexpr int PROW  = Wn * PK;     // 154 floats per d-row in smem
constexpr int SLABP = Dn * PROW;   // 1232 floats per padded slab
constexpr int NT    = 256;
constexpr int SUBK  = 26;          // ceil(0.8 * 32)
constexpr int NOPS  = 560;         // cp.async ops per slab (8x(56x8B + 14x4B))
constexpr int PW    = 15;          // padded W stride for phase-2 arrays
}

__device__ __forceinline__ void cp_async8(void* sm, const void* gm) {
    unsigned s = (unsigned)__cvta_generic_to_shared(sm);
    asm volatile("cp.async.ca.shared.global [%0], [%1], 8;\n" :: "r"(s), "l"(gm));
}
__device__ __forceinline__ void cp_async4(void* sm, const void* gm) {
    unsigned s = (unsigned)__cvta_generic_to_shared(sm);
    asm volatile("cp.async.ca.shared.global [%0], [%1], 4;\n" :: "r"(s), "l"(gm));
}
__device__ __forceinline__ void cp_commit() {
    asm volatile("cp.async.commit_group;\n");
}
template <int N>
__device__ __forceinline__ void cp_wait() {
    asm volatile("cp.async.wait_group %0;\n" :: "n"(N));
}

__device__ __forceinline__ float fsqrt_ap(float x) {
    float r; asm("sqrt.approx.f32 %0, %1;" : "=f"(r) : "f"(x)); return r;
}
__device__ __forceinline__ float frcp_ap(float x) {
    float r; asm("rcp.approx.f32 %0, %1;" : "=f"(r) : "f"(x)); return r;
}

// Monotone float -> uint key: a <= b  <=>  fkey(a) <= fkey(b)
__device__ __forceinline__ unsigned fkey(float f) {
    unsigned u = __float_as_uint(f);
    return u ^ (unsigned)(((int)u >> 31) | 0x80000000);
}

__global__ void __launch_bounds__(NT)
caps_route_kernel(const float* __restrict__ x, float* __restrict__ out) {
    const int h = blockIdx.x, o = blockIdx.y, b = blockIdx.z;
    const int tid = threadIdx.x;

    __shared__ __align__(16) float sl[3][SLABP];   // cp.async ring (k padded to 11)
    __shared__ float    sNorm[PROW];               // norms, [w*11 + k]
    __shared__ float    sXavg[In * Dn * PW];       // [i][d][w], w padded to 15
    __shared__ float    sNI[In * PW];              // [i][w]
    __shared__ float    sRsum[Wn];
    __shared__ float    sV[Dn * PW];
    __shared__ float    sLoss[In * PW];
    __shared__ unsigned sThr[Wn];
    __shared__ float    sRfin[Wn];

    const long strideD = (long)Hn * Wn * Kn;       // 1764
    const long strideO = Dn * strideD;             // 14112
    const long strideI = On * strideO;             // 451584
    const long strideB = In * strideI;             // 14450688
    const float* base = x + (long)b * strideB + (long)o * strideO + (long)h * WK;

    // ---- hoisted cp.async op table (<=3 ops per thread, fixed across slabs) ----
    long gOffA[3]; int sOffA[3]; bool is8A[3];
    #pragma unroll
    for (int q = 0; q < 3; ++q) {
        int j = tid + q * NT;
        if (j < NOPS) {
            int r = j / 70, m = j - 70 * r;        // r = d-row, m = op within row
            int f, w, k; bool e8;
            if (m < 56) {                          // 8B granule, m-th even c skipping straddles
                int g9 = m >> 3, rem = m & 7;
                int c = 9 * g9 + rem + (rem >= 4 ? 1 : 0);
                f = 2 * c; w = f / 9; k = f - 9 * w; e8 = true;
            } else {                               // straddle halves: 4B each
                int s2 = m - 56, tp = s2 >> 1, half = s2 & 1;
                w = 2 * tp + half; k = half ? 0 : 8; f = 9 * w + k; e8 = false;
            }
            gOffA[q] = (long)r * strideD + f;
            sOffA[q] = r * PROW + w * PK + k;
            is8A[q]  = e8;
        }
    }
    const bool has2 = (tid < NOPS - 2 * NT);       // tid < 48

    auto prefetch = [&](int slab, float* buf) {
        const float* g = base + (long)slab * strideI;
        if (is8A[0]) cp_async8(buf + sOffA[0], g + gOffA[0]);
        else         cp_async4(buf + sOffA[0], g + gOffA[0]);
        if (is8A[1]) cp_async8(buf + sOffA[1], g + gOffA[1]);
        else         cp_async4(buf + sOffA[1], g + gOffA[1]);
        if (has2) {
            if (is8A[2]) cp_async8(buf + sOffA[2], g + gOffA[2]);
            else         cp_async4(buf + sOffA[2], g + gOffA[2]);
        }
    };

    // Region A: 126 threads, one per (w, k)
    const bool actA = (tid < WK);
    const int wA = tid / Kn, kA = tid - Kn * wA;
    const int wkA = wA * PK + kA;
    // Region C: 112 threads, one per (d, w)
    const bool actC = (tid < Dn * Wn);
    const int dC = tid / Wn, wC = tid - Wn * dC;
    const int xoC = dC * PROW + wC * PK;
    const int noC = wC * PK;

    // ---- prologue ----
    prefetch(0, sl[0]); cp_commit();
    prefetch(1, sl[1]); cp_commit();
    if (tid < Wn) sThr[tid] = 0u;

    int bufi = 0;
    // ---- Phase 1: per capsule kernel-position weighted average ----
    for (int i = 0; i < In; ++i) {
        cp_wait<1>();          // slab i complete (one group may remain in flight)
        __syncthreads();       // data visible; prior compute finished with reused buffer

        int nx = i + 2;
        if (nx < In) {
            int nb = bufi + 2; if (nb >= 3) nb -= 3;
            prefetch(nx, sl[nb]);
        }
        cp_commit();           // (possibly empty) group keeps wait-count in lockstep

        const float* s = sl[bufi];

        if (actA) {            // norms over D per (w,k) — conflict-free (stride 11)
            float ss = 0.f;
            #pragma unroll
            for (int d = 0; d < Dn; ++d) {
                float v = s[d * PROW + wkA];
                ss += v * v;
            }
            sNorm[wkA] = fsqrt_ap(ss);
        }
        __syncthreads();

        if (actC) {            // xavg[d][w]; all LDS 1-wavefront
            float num = 0.f, den = 0.f;
            #pragma unroll
            for (int k = 0; k < Kn; ++k) {
                float nk = sNorm[noC + k];
                num += nk * s[xoC + k];
                den += nk;
            }
            sXavg[(i * Dn + dC) * PW + wC] = num * frcp_ap(den);
        }

        ++bufi; if (bufi == 3) bufi = 0;
    }
    __syncthreads();

    // ---- Phase 2: reductions over input capsules ----
    for (int p = tid; p < In * Wn; p += NT) {
        int i = p / Wn, w = p - Wn * i;
        float acc = 0.f;
        #pragma unroll
        for (int d = 0; d < Dn; ++d) {
            float v = sXavg[(i * Dn + d) * PW + w];
            acc += v * v;
        }
        sNI[i * PW + w] = fsqrt_ap(acc);
    }
    __syncthreads();

    if (tid < Wn) {
        float sum = 0.f;
        #pragma unroll 4
        for (int i = 0; i < In; ++i) sum += sNI[i * PW + tid];
        sRsum[tid] = frcp_ap(sum);
    }
    __syncthreads();

    if (actC) {                // consensus v[d][w]
        float num = 0.f;
        #pragma unroll 4
        for (int i = 0; i < In; ++i)
            num += sNI[i * PW + wC] * sXavg[(i * Dn + dC) * PW + wC];
        sV[dC * PW + wC] = num * sRsum[wC];
    }
    __syncthreads();

    for (int p = tid; p < In * Wn; p += NT) {   // losses
        int i = p / Wn, w = p - Wn * i;
        float acc = 0.f;
        #pragma unroll
        for (int d = 0; d < Dn; ++d)
            acc += sV[d * PW + w] * sXavg[(i * Dn + d) * PW + w];
        sLoss[i * PW + w] = -acc;
    }
    __syncthreads();

    // kth-smallest threshold (k = SUBK), exact tie semantics
    for (int p = tid; p < In * Wn; p += NT) {
        int i = p / Wn, w = p - Wn * i;
        float mine = sLoss[i * PW + w];
        int cnt = 0;
        #pragma unroll 8
        for (int j = 0; j < In; ++j)
            cnt += (sLoss[j * PW + w] < mine);
        if (cnt <= SUBK - 1)
            atomicMax(&sThr[w], fkey(mine));
    }
    __syncthreads();

    if (tid < Wn) {            // masked denominator reciprocal
        const unsigned thr = sThr[tid];
        float den = 0.f;
        #pragma unroll 4
        for (int i = 0; i < In; ++i)
            if (fkey(sLoss[i * PW + tid]) <= thr) den += sNI[i * PW + tid];
        sRfin[tid] = frcp_ap(den);
    }
    __syncthreads();

    if (actC) {                // masked re-average, write output
        const unsigned thr = sThr[wC];
        float num = 0.f;
        #pragma unroll 4
        for (int i = 0; i < In; ++i) {
            if (fkey(sLoss[i * PW + wC]) <= thr)
                num += sNI[i * PW + wC] * sXavg[(i * Dn + dC) * PW + wC];
        }
        out[(((long)b * On + o) * Dn + dC) * (Hn * Wn) + h * Wn + wC] = num * sRfin[wC];
    }
}

extern "C" void kernel_launch(void* const* d_in, const int* in_sizes, int n_in,
                              void* d_out, int out_size) {
    const float* x = (const float*)d_in[0];
    float* out = (float*)d_out;
    dim3 grid(Hn, On, Bn);   // 14 x 32 x 8 = 3584 CTAs
    caps_route_kernel<<<grid, NT>>>(x, out);
}